// round 16
// baseline (speedup 1.0000x reference)
#include <cuda_runtime.h>
#include <cuda_bf16.h>
#include <cuda_fp16.h>
#include <cstdint>

#define F_IN 128
#define F_OUT 64
#define MAX_NODES 50000

// Scratch (no runtime allocation allowed): projected features in fp16.
__device__ __half g_hwh[(size_t)MAX_NODES * F_OUT];

// ---------------------------------------------------------------------------
// TF32 / cp.async helpers
// ---------------------------------------------------------------------------
__device__ __forceinline__ unsigned cvt_tf32(float x) {
    unsigned r;
    asm("cvt.rna.tf32.f32 %0, %1;" : "=r"(r) : "f"(x));
    return r;
}

#define MMA_TF32(d, a0, a1, a2, a3, b0, b1)                                  \
    asm("mma.sync.aligned.m16n8k8.row.col.f32.tf32.tf32.f32 "                \
        "{%0,%1,%2,%3}, {%4,%5,%6,%7}, {%8,%9}, {%0,%1,%2,%3};"              \
        : "+f"(d[0]), "+f"(d[1]), "+f"(d[2]), "+f"(d[3])                     \
        : "r"(a0), "r"(a1), "r"(a2), "r"(a3), "r"(b0), "r"(b1))

__device__ __forceinline__ unsigned smem_u32(const void* p) {
    return (unsigned)__cvta_generic_to_shared(p);
}
#define CP_ASYNC16Z(s, g, n) \
    asm volatile("cp.async.cg.shared.global [%0], [%1], 16, %2;" \
                 :: "r"(s), "l"(g), "r"(n))
#define CP_COMMIT() asm volatile("cp.async.commit_group;")
#define CP_WAIT0()  asm volatile("cp.async.wait_group 0;" ::: "memory")
#define CP_WAIT1()  asm volatile("cp.async.wait_group 1;" ::: "memory")

// ---------------------------------------------------------------------------
// Kernel 1: fused TF32 tensor-core GEMM + bias-init — single-pass TF32.
//   g_hwh[N,64] = fp16(h[N,128] @ (W0+W1)) ;  out[N,64] = bias
// Frozen (measured near DRAM/staging floor). Error budget: tf32 (~4e-4) +
// fp16 store (~1.7e-4) -> measured 2.9e-4 total, < 1e-3.
// ---------------------------------------------------------------------------
#define GR 64
#define KC 32
#define NCHUNK (F_IN / KC)
#define HS_S 36
#define WS_S 72
__global__ void __launch_bounds__(128) gemm_tc_kernel(
        const float* __restrict__ h,
        const float* __restrict__ w,
        const float* __restrict__ bias,
        float* __restrict__ out,
        int n_nodes) {
    __shared__ __align__(16) float hs[2][GR][HS_S]; // 18.4 KB: A double buffer
    __shared__ __align__(16) float ws[KC][WS_S];    // 9.2 KB: tf32(W0+W1) [k][n]
    __shared__ __align__(16) float bs[F_OUT];

    int tid  = threadIdx.x;
    int lane = tid & 31;
    int warp = tid >> 5;
    int g = lane >> 2;
    int t = lane & 3;
    int row0 = blockIdx.x * GR;
    int wr0  = warp * 16;

    if (tid < F_OUT) bs[tid] = bias[tid];

    #define STAGE_A(buf, k0_)                                                  \
        do {                                                                   \
            _Pragma("unroll")                                                  \
            for (int i_ = tid; i_ < GR * (KC / 4); i_ += 128) {                \
                int r_ = i_ >> 3;                                              \
                int c_ = i_ & 7;                                               \
                int gr_ = row0 + r_;                                           \
                bool v_ = (gr_ < n_nodes);                                     \
                const char* gp_ = (const char*)(h +                            \
                    (size_t)(v_ ? gr_ : 0) * F_IN + (k0_)) + c_ * 16;          \
                CP_ASYNC16Z(smem_u32(&hs[buf][r_][4 * c_]), gp_, v_ ? 16 : 0); \
            }                                                                  \
        } while (0)

    STAGE_A(0, 0);
    CP_COMMIT();

    float acc[8][4];
    #pragma unroll
    for (int nt = 0; nt < 8; nt++)
        #pragma unroll
        for (int i = 0; i < 4; i++) acc[nt][i] = 0.0f;

    int pb = 0;
    #pragma unroll
    for (int chunk = 0; chunk < NCHUNK; chunk++) {
        int k0 = chunk * KC;

        if (chunk + 1 < NCHUNK) {
            STAGE_A(pb ^ 1, k0 + KC);
            CP_COMMIT();
        }

        // Synchronous W-chunk stage (L2-hot): sum, tf32-round, store
        #pragma unroll
        for (int i = tid; i < KC * (F_OUT / 4); i += 128) {
            int k = i >> 4;
            int q = i & 15;
            const float4* w0 = (const float4*)(w + (size_t)(k0 + k) * F_OUT);
            const float4* w1 = (const float4*)(w + (size_t)F_IN * F_OUT + (size_t)(k0 + k) * F_OUT);
            float4 s0 = w0[q], s1 = w1[q];
            ws[k][4 * q + 0] = __uint_as_float(cvt_tf32(s0.x + s1.x));
            ws[k][4 * q + 1] = __uint_as_float(cvt_tf32(s0.y + s1.y));
            ws[k][4 * q + 2] = __uint_as_float(cvt_tf32(s0.z + s1.z));
            ws[k][4 * q + 3] = __uint_as_float(cvt_tf32(s0.w + s1.w));
        }

        if (chunk + 1 < NCHUNK) { CP_WAIT1(); } else { CP_WAIT0(); }
        __syncthreads();

        #pragma unroll
        for (int ks = 0; ks < KC; ks += 8) {
            unsigned ah0 = cvt_tf32(hs[pb][wr0 + g][ks + t]);
            unsigned ah1 = cvt_tf32(hs[pb][wr0 + g + 8][ks + t]);
            unsigned ah2 = cvt_tf32(hs[pb][wr0 + g][ks + t + 4]);
            unsigned ah3 = cvt_tf32(hs[pb][wr0 + g + 8][ks + t + 4]);

            #pragma unroll
            for (int nt = 0; nt < 8; nt++) {
                int n = 8 * nt + g;
                unsigned bh0 = __float_as_uint(ws[ks + t][n]);
                unsigned bh1 = __float_as_uint(ws[ks + t + 4][n]);
                MMA_TF32(acc[nt], ah0, ah1, ah2, ah3, bh0, bh1);
            }
        }
        __syncthreads();
        pb ^= 1;
    }
    #undef STAGE_A

    int r1 = row0 + wr0 + g;
    int r2 = r1 + 8;
    #pragma unroll
    for (int nt = 0; nt < 8; nt++) {
        int c = 8 * nt + 2 * t;
        float2 bv = make_float2(bs[c], bs[c + 1]);
        if (r1 < n_nodes) {
            *(__half2*)&g_hwh[(size_t)r1 * F_OUT + c] =
                __floats2half2_rn(acc[nt][0], acc[nt][1]);
            *(float2*)&out[(size_t)r1 * F_OUT + c] = bv;
        }
        if (r2 < n_nodes) {
            *(__half2*)&g_hwh[(size_t)r2 * F_OUT + c] =
                __floats2half2_rn(acc[nt][2], acc[nt][3]);
            *(float2*)&out[(size_t)r2 * F_OUT + c] = bv;
        }
    }
}

// ---------------------------------------------------------------------------
// Edge phase core math (shared): softmax w/o max-sub, fp16 gather, RED.v4.
// ---------------------------------------------------------------------------
__device__ __forceinline__ void edge_pair_body(
        const float* __restrict__ ef, float* __restrict__ out,
        int siA, int diA, int siB, int diB,
        int ecA, int ecB, bool vA, bool vB, int sl) {
    const float4* ef4 = (const float4*)ef;
    float4 a = __ldcs(ef4 + (size_t)ecA * (F_OUT / 4) + sl);
    float4 b = __ldcs(ef4 + (size_t)ecB * (F_OUT / 4) + sl);

    const uint2* hwv = (const uint2*)g_hwh;
    uint2 rA = __ldg(hwv + (size_t)siA * 16 + sl);
    uint2 rB = __ldg(hwv + (size_t)siB * 16 + sl);
    float2 hA01 = __half22float2(*(const __half2*)&rA.x);
    float2 hA23 = __half22float2(*(const __half2*)&rA.y);
    float2 hB01 = __half22float2(*(const __half2*)&rB.x);
    float2 hB23 = __half22float2(*(const __half2*)&rB.y);

    float a0 = __expf(a.x), a1 = __expf(a.y), a2 = __expf(a.z), a3 = __expf(a.w);
    float b0 = __expf(b.x), b1 = __expf(b.y), b2 = __expf(b.z), b3 = __expf(b.w);
    float sA = a0 + a1 + a2 + a3;
    float sB = b0 + b1 + b2 + b3;
    #pragma unroll
    for (int o = 8; o; o >>= 1) {
        sA += __shfl_xor_sync(0xffffffffu, sA, o);
        sB += __shfl_xor_sync(0xffffffffu, sB, o);
    }
    float iA = __fdividef(1.0f, sA);
    float iB = __fdividef(1.0f, sB);

    if (vA) {
        float* p = out + (size_t)diA * F_OUT + 4 * sl;
        asm volatile("red.global.add.v4.f32 [%0], {%1, %2, %3, %4};"
                     :: "l"(p), "f"(hA01.x * a0 * iA), "f"(hA01.y * a1 * iA),
                        "f"(hA23.x * a2 * iA), "f"(hA23.y * a3 * iA) : "memory");
    }
    if (vB) {
        float* p = out + (size_t)diB * F_OUT + 4 * sl;
        asm volatile("red.global.add.v4.f32 [%0], {%1, %2, %3, %4};"
                     :: "l"(p), "f"(hB01.x * b0 * iB), "f"(hB01.y * b1 * iB),
                        "f"(hB23.x * b2 * iB), "f"(hB23.y * b3 * iB) : "memory");
    }
}

// Fast path: n_edges % 4 == 0, exact grid cover. src/dst quads for the
// warp's 4 consecutive edges fetched as ONE warp-uniform LDG.128 each
// (broadcast, 1 wavefront) instead of 4 scalar LDG.32 per lane.
__global__ void __launch_bounds__(256) edge_kernel_fast(
        const float* __restrict__ ef,
        const int* __restrict__ src,
        const int* __restrict__ dst,
        float* __restrict__ out) {
    int gw   = (blockIdx.x * blockDim.x + threadIdx.x) >> 5;
    int lane = threadIdx.x & 31;
    int grp  = lane >> 4;
    int sl   = lane & 15;

    int4 s4 = __ldg((const int4*)src + gw);   // src[4gw .. 4gw+3]
    int4 d4 = __ldg((const int4*)dst + gw);
    // group0: edges 4gw (.x), 4gw+2 (.z); group1: 4gw+1 (.y), 4gw+3 (.w)
    int siA = grp ? s4.y : s4.x;
    int siB = grp ? s4.w : s4.z;
    int diA = grp ? d4.y : d4.x;
    int diB = grp ? d4.w : d4.z;

    int eA = 4 * gw + grp;
    edge_pair_body(ef, out, siA, diA, siB, diB, eA, eA + 2, true, true, sl);
}

// General path: bounds-checked scalar index loads (any n_edges).
__global__ void edge_kernel(const float* __restrict__ ef,
                            const int* __restrict__ src,
                            const int* __restrict__ dst,
                            float* __restrict__ out,
                            int n_edges) {
    int gw   = (blockIdx.x * blockDim.x + threadIdx.x) >> 5;
    int lane = threadIdx.x & 31;
    int grp  = lane >> 4;
    int sl   = lane & 15;

    int eA = 4 * gw + grp;
    int eB = eA + 2;
    bool vA = (eA < n_edges), vB = (eB < n_edges);
    int ecA = vA ? eA : 0;
    int ecB = vB ? eB : 0;
    int siA = __ldg(src + ecA), diA = __ldg(dst + ecA);
    int siB = __ldg(src + ecB), diB = __ldg(dst + ecB);
    edge_pair_body(ef, out, siA, diA, siB, diB, ecA, ecB, vA, vB, sl);
}

// ---------------------------------------------------------------------------
extern "C" void kernel_launch(void* const* d_in, const int* in_sizes, int n_in,
                              void* d_out, int out_size) {
    const float* h    = (const float*)d_in[0];
    const float* ef   = (const float*)d_in[1];
    const float* w    = (const float*)d_in[2];
    const float* bias = (const float*)d_in[3];
    const int*   src  = (const int*)d_in[4];
    const int*   dst  = (const int*)d_in[5];
    float* out = (float*)d_out;

    int n_nodes = in_sizes[0] / F_IN;
    int n_edges = in_sizes[4];

    gemm_tc_kernel<<<(n_nodes + GR - 1) / GR, 128>>>(h, w, bias, out, n_nodes);

    if (n_edges % 4 == 0 && (n_edges / 4) % 8 == 0) {
        edge_kernel_fast<<<n_edges / 32, 256>>>(ef, src, dst, out);
    } else {
        int warps  = (n_edges + 3) / 4;
        int blocks = (warps * 32 + 255) / 256;
        edge_kernel<<<blocks, 256>>>(ef, src, dst, out, n_edges);
    }
}

// round 17
// speedup vs baseline: 1.0266x; 1.0266x over previous
#include <cuda_runtime.h>
#include <cuda_bf16.h>
#include <cuda_fp16.h>
#include <cstdint>

#define F_IN 128
#define F_OUT 64
#define MAX_NODES 50000

// Scratch (no runtime allocation allowed): projected features in fp16.
__device__ __half g_hwh[(size_t)MAX_NODES * F_OUT];

// ---------------------------------------------------------------------------
// TF32 / cp.async helpers
// ---------------------------------------------------------------------------
__device__ __forceinline__ unsigned cvt_tf32(float x) {
    unsigned r;
    asm("cvt.rna.tf32.f32 %0, %1;" : "=r"(r) : "f"(x));
    return r;
}

#define MMA_TF32(d, a0, a1, a2, a3, b0, b1)                                  \
    asm("mma.sync.aligned.m16n8k8.row.col.f32.tf32.tf32.f32 "                \
        "{%0,%1,%2,%3}, {%4,%5,%6,%7}, {%8,%9}, {%0,%1,%2,%3};"              \
        : "+f"(d[0]), "+f"(d[1]), "+f"(d[2]), "+f"(d[3])                     \
        : "r"(a0), "r"(a1), "r"(a2), "r"(a3), "r"(b0), "r"(b1))

__device__ __forceinline__ unsigned smem_u32(const void* p) {
    return (unsigned)__cvta_generic_to_shared(p);
}
#define CP_ASYNC16Z(s, g, n) \
    asm volatile("cp.async.cg.shared.global [%0], [%1], 16, %2;" \
                 :: "r"(s), "l"(g), "r"(n))
#define CP_COMMIT() asm volatile("cp.async.commit_group;")
#define CP_WAIT0()  asm volatile("cp.async.wait_group 0;" ::: "memory")
#define CP_WAIT1()  asm volatile("cp.async.wait_group 1;" ::: "memory")

// ---------------------------------------------------------------------------
// Kernel 1: fused TF32 tensor-core GEMM + bias-init — single-pass TF32.
//   g_hwh[N,64] = fp16(h[N,128] @ (W0+W1)) ;  out[N,64] = bias
// Frozen (near DRAM/staging floor). Error: tf32 + fp16 -> measured 2.9e-4.
// ---------------------------------------------------------------------------
#define GR 64
#define KC 32
#define NCHUNK (F_IN / KC)
#define HS_S 36
#define WS_S 72
__global__ void __launch_bounds__(128) gemm_tc_kernel(
        const float* __restrict__ h,
        const float* __restrict__ w,
        const float* __restrict__ bias,
        float* __restrict__ out,
        int n_nodes) {
    __shared__ __align__(16) float hs[2][GR][HS_S]; // 18.4 KB: A double buffer
    __shared__ __align__(16) float ws[KC][WS_S];    // 9.2 KB: tf32(W0+W1) [k][n]
    __shared__ __align__(16) float bs[F_OUT];

    int tid  = threadIdx.x;
    int lane = tid & 31;
    int warp = tid >> 5;
    int g = lane >> 2;
    int t = lane & 3;
    int row0 = blockIdx.x * GR;
    int wr0  = warp * 16;

    if (tid < F_OUT) bs[tid] = bias[tid];

    #define STAGE_A(buf, k0_)                                                  \
        do {                                                                   \
            _Pragma("unroll")                                                  \
            for (int i_ = tid; i_ < GR * (KC / 4); i_ += 128) {                \
                int r_ = i_ >> 3;                                              \
                int c_ = i_ & 7;                                               \
                int gr_ = row0 + r_;                                           \
                bool v_ = (gr_ < n_nodes);                                     \
                const char* gp_ = (const char*)(h +                            \
                    (size_t)(v_ ? gr_ : 0) * F_IN + (k0_)) + c_ * 16;          \
                CP_ASYNC16Z(smem_u32(&hs[buf][r_][4 * c_]), gp_, v_ ? 16 : 0); \
            }                                                                  \
        } while (0)

    STAGE_A(0, 0);
    CP_COMMIT();

    float acc[8][4];
    #pragma unroll
    for (int nt = 0; nt < 8; nt++)
        #pragma unroll
        for (int i = 0; i < 4; i++) acc[nt][i] = 0.0f;

    int pb = 0;
    #pragma unroll
    for (int chunk = 0; chunk < NCHUNK; chunk++) {
        int k0 = chunk * KC;

        if (chunk + 1 < NCHUNK) {
            STAGE_A(pb ^ 1, k0 + KC);
            CP_COMMIT();
        }

        // Synchronous W-chunk stage (L2-hot): sum, tf32-round, store
        #pragma unroll
        for (int i = tid; i < KC * (F_OUT / 4); i += 128) {
            int k = i >> 4;
            int q = i & 15;
            const float4* w0 = (const float4*)(w + (size_t)(k0 + k) * F_OUT);
            const float4* w1 = (const float4*)(w + (size_t)F_IN * F_OUT + (size_t)(k0 + k) * F_OUT);
            float4 s0 = w0[q], s1 = w1[q];
            ws[k][4 * q + 0] = __uint_as_float(cvt_tf32(s0.x + s1.x));
            ws[k][4 * q + 1] = __uint_as_float(cvt_tf32(s0.y + s1.y));
            ws[k][4 * q + 2] = __uint_as_float(cvt_tf32(s0.z + s1.z));
            ws[k][4 * q + 3] = __uint_as_float(cvt_tf32(s0.w + s1.w));
        }

        if (chunk + 1 < NCHUNK) { CP_WAIT1(); } else { CP_WAIT0(); }
        __syncthreads();

        #pragma unroll
        for (int ks = 0; ks < KC; ks += 8) {
            unsigned ah0 = cvt_tf32(hs[pb][wr0 + g][ks + t]);
            unsigned ah1 = cvt_tf32(hs[pb][wr0 + g + 8][ks + t]);
            unsigned ah2 = cvt_tf32(hs[pb][wr0 + g][ks + t + 4]);
            unsigned ah3 = cvt_tf32(hs[pb][wr0 + g + 8][ks + t + 4]);

            #pragma unroll
            for (int nt = 0; nt < 8; nt++) {
                int n = 8 * nt + g;
                unsigned bh0 = __float_as_uint(ws[ks + t][n]);
                unsigned bh1 = __float_as_uint(ws[ks + t + 4][n]);
                MMA_TF32(acc[nt], ah0, ah1, ah2, ah3, bh0, bh1);
            }
        }
        __syncthreads();
        pb ^= 1;
    }
    #undef STAGE_A

    int r1 = row0 + wr0 + g;
    int r2 = r1 + 8;
    #pragma unroll
    for (int nt = 0; nt < 8; nt++) {
        int c = 8 * nt + 2 * t;
        float2 bv = make_float2(bs[c], bs[c + 1]);
        if (r1 < n_nodes) {
            *(__half2*)&g_hwh[(size_t)r1 * F_OUT + c] =
                __floats2half2_rn(acc[nt][0], acc[nt][1]);
            *(float2*)&out[(size_t)r1 * F_OUT + c] = bv;
        }
        if (r2 < n_nodes) {
            *(__half2*)&g_hwh[(size_t)r2 * F_OUT + c] =
                __floats2half2_rn(acc[nt][2], acc[nt][3]);
            *(float2*)&out[(size_t)r2 * F_OUT + c] = bv;
        }
    }
}

// ---------------------------------------------------------------------------
// Edge phase (round-15 form — measured optimum — split around a PDL grid
// dependency: ef stream + softmax BEFORE cudaGridDependencySynchronize();
// g_hwh gather + RED after. Launched with programmatic stream serialization
// so its front half overlaps the tail of the GEMM.
// ---------------------------------------------------------------------------
__device__ __forceinline__ void edge_pair(
        const float* __restrict__ ef, const int* __restrict__ src,
        const int* __restrict__ dst, float* __restrict__ out,
        int ecA, int ecB, bool vA, bool vB, int sl) {
    // ---- GEMM-independent front: indices, ef stream, softmax ----
    int siA = __ldg(src + ecA), diA = __ldg(dst + ecA);
    int siB = __ldg(src + ecB), diB = __ldg(dst + ecB);

    const float4* ef4 = (const float4*)ef;
    float4 a = __ldcs(ef4 + (size_t)ecA * (F_OUT / 4) + sl);
    float4 b = __ldcs(ef4 + (size_t)ecB * (F_OUT / 4) + sl);

    float a0 = __expf(a.x), a1 = __expf(a.y), a2 = __expf(a.z), a3 = __expf(a.w);
    float b0 = __expf(b.x), b1 = __expf(b.y), b2 = __expf(b.z), b3 = __expf(b.w);
    float sA = a0 + a1 + a2 + a3;
    float sB = b0 + b1 + b2 + b3;
    #pragma unroll
    for (int o = 8; o; o >>= 1) {
        sA += __shfl_xor_sync(0xffffffffu, sA, o);
        sB += __shfl_xor_sync(0xffffffffu, sB, o);
    }
    float iA = __fdividef(1.0f, sA);
    float iB = __fdividef(1.0f, sB);

    // ---- wait for GEMM's g_hwh + bias-init writes to be visible ----
    cudaGridDependencySynchronize();

    const uint2* hwv = (const uint2*)g_hwh;
    uint2 rA = __ldg(hwv + (size_t)siA * 16 + sl);
    uint2 rB = __ldg(hwv + (size_t)siB * 16 + sl);
    float2 hA01 = __half22float2(*(const __half2*)&rA.x);
    float2 hA23 = __half22float2(*(const __half2*)&rA.y);
    float2 hB01 = __half22float2(*(const __half2*)&rB.x);
    float2 hB23 = __half22float2(*(const __half2*)&rB.y);

    if (vA) {
        float* p = out + (size_t)diA * F_OUT + 4 * sl;
        asm volatile("red.global.add.v4.f32 [%0], {%1, %2, %3, %4};"
                     :: "l"(p), "f"(hA01.x * a0 * iA), "f"(hA01.y * a1 * iA),
                        "f"(hA23.x * a2 * iA), "f"(hA23.y * a3 * iA) : "memory");
    }
    if (vB) {
        float* p = out + (size_t)diB * F_OUT + 4 * sl;
        asm volatile("red.global.add.v4.f32 [%0], {%1, %2, %3, %4};"
                     :: "l"(p), "f"(hB01.x * b0 * iB), "f"(hB01.y * b1 * iB),
                        "f"(hB23.x * b2 * iB), "f"(hB23.y * b3 * iB) : "memory");
    }
}

// Fast path: exact grid cover, zero bounds logic.
__global__ void __launch_bounds__(256) edge_kernel_fast(
        const float* __restrict__ ef,
        const int* __restrict__ src,
        const int* __restrict__ dst,
        float* __restrict__ out) {
    int gw   = (blockIdx.x * blockDim.x + threadIdx.x) >> 5;
    int lane = threadIdx.x & 31;
    int grp  = lane >> 4;
    int sl   = lane & 15;
    int eA = 4 * gw + grp;
    edge_pair(ef, src, dst, out, eA, eA + 2, true, true, sl);
}

// General path: bounds-checked (clamped for convergence).
__global__ void edge_kernel(const float* __restrict__ ef,
                            const int* __restrict__ src,
                            const int* __restrict__ dst,
                            float* __restrict__ out,
                            int n_edges) {
    int gw   = (blockIdx.x * blockDim.x + threadIdx.x) >> 5;
    int lane = threadIdx.x & 31;
    int grp  = lane >> 4;
    int sl   = lane & 15;

    int eA = 4 * gw + grp;
    int eB = eA + 2;
    bool vA = (eA < n_edges), vB = (eB < n_edges);
    edge_pair(ef, src, dst, out, vA ? eA : 0, vB ? eB : 0, vA, vB, sl);
}

// ---------------------------------------------------------------------------
extern "C" void kernel_launch(void* const* d_in, const int* in_sizes, int n_in,
                              void* d_out, int out_size) {
    const float* h    = (const float*)d_in[0];
    const float* ef   = (const float*)d_in[1];
    const float* w    = (const float*)d_in[2];
    const float* bias = (const float*)d_in[3];
    const int*   src  = (const int*)d_in[4];
    const int*   dst  = (const int*)d_in[5];
    float* out = (float*)d_out;

    int n_nodes = in_sizes[0] / F_IN;
    int n_edges = in_sizes[4];

    gemm_tc_kernel<<<(n_nodes + GR - 1) / GR, 128>>>(h, w, bias, out, n_nodes);

    if (n_edges % 4 == 0 && (n_edges / 4) % 8 == 0) {
        // PDL: edge blocks may co-schedule into SM slots the GEMM leaves
        // idle; the grid-dependency sync inside the kernel orders the
        // g_hwh/out consumption after the GEMM's writes.
        cudaLaunchConfig_t cfg = {};
        cfg.gridDim  = dim3(n_edges / 32, 1, 1);
        cfg.blockDim = dim3(256, 1, 1);
        cudaLaunchAttribute attrs[1];
        attrs[0].id = cudaLaunchAttributeProgrammaticStreamSerialization;
        attrs[0].val.programmaticStreamSerializationAllowed = 1;
        cfg.attrs = attrs;
        cfg.numAttrs = 1;
        cudaLaunchKernelEx(&cfg, edge_kernel_fast, ef, src, dst, out);
    } else {
        int warps  = (n_edges + 3) / 4;
        int blocks = (warps * 32 + 255) / 256;
        edge_kernel<<<blocks, 256>>>(ef, src, dst, out, n_edges);
    }
}